// round 13
// baseline (speedup 1.0000x reference)
#include <cuda_runtime.h>
#include <cuda_fp16.h>
#include <cstdint>

// RNN h_t = tanh([x_t,h_{t-1}]@Wc + bc); out = h_T@Wo + bo
// B=4096, T=128, D=128, H=150, O=10.
// R13: single-pass fp16 mma.sync, weights in registers, and TWO independent
// batch groups (16 rows each) per CTA, software-pipelined with per-group
// mbarriers: each group's barrier wait hides under the other group's compute.

#define T_SEQ 128
#define D_IN  128
#define H_HID 150
#define O_OUT 10
#define M_BLK 32
#define MG    16             // rows per group
#define NPAD  160            // 20 n8-tiles
#define KTILES 18            // K = 288
#define ASTR  296            // row stride in fp16 elems (592 B, ldmatrix conflict-free)
#define ASTRB 592
#define NTHR  256

// SMEM byte offsets
#define ABUFSZ  9472                   // 16*592
#define AG0     0                      // G0: buf0 @0, buf1 @9472
#define AG1     18944                  // G1: buf0 @18944, buf1 @28416
#define SM_W    37888                  // +4*ABUFSZ
#define SM_BIAS 132608                 // +160*592
#define SM_HF   133248                 // +640 ; fp32 h stash [32][160]
#define SM_MB   153728                 // +32*640 ; 2 mbarriers
#define SMEM_BYTES 153744

typedef unsigned int u32;

__device__ __forceinline__ u32 smem_u32(const void* p) {
    u32 a;
    asm("{ .reg .u64 t; cvta.to.shared.u64 t, %1; cvt.u32.u64 %0, t; }" : "=r"(a) : "l"(p));
    return a;
}
__device__ __forceinline__ void ldsm_x4(u32* r, u32 addr) {
    asm volatile("ldmatrix.sync.aligned.m8n8.x4.shared.b16 {%0,%1,%2,%3}, [%4];"
        : "=r"(r[0]), "=r"(r[1]), "=r"(r[2]), "=r"(r[3]) : "r"(addr));
}
__device__ __forceinline__ void ldsm_x2(u32* r, u32 addr) {
    asm volatile("ldmatrix.sync.aligned.m8n8.x2.shared.b16 {%0,%1}, [%2];"
        : "=r"(r[0]), "=r"(r[1]) : "r"(addr));
}
__device__ __forceinline__ void mma_f16(float* c, const u32* a, u32 b0, u32 b1) {
    asm volatile("mma.sync.aligned.m16n8k16.row.col.f32.f16.f16.f32 "
        "{%0,%1,%2,%3}, {%4,%5,%6,%7}, {%8,%9}, {%0,%1,%2,%3};"
        : "+f"(c[0]), "+f"(c[1]), "+f"(c[2]), "+f"(c[3])
        : "r"(a[0]), "r"(a[1]), "r"(a[2]), "r"(a[3]), "r"(b0), "r"(b1));
}
__device__ __forceinline__ u32 cvt2h(float a, float b) {   // pack fp16x2 (lo=a, hi=b)
    u32 r;
    asm("cvt.rn.f16x2.f32 %0, %1, %2;" : "=r"(r) : "f"(b), "f"(a));
    return r;
}
__device__ __forceinline__ float htanh(float x) {          // MUFU.TANH
    float r;
    asm("tanh.approx.f32 %0, %1;" : "=f"(r) : "f"(x));
    return r;
}
__device__ __forceinline__ void mbar_init(u32 a, u32 cnt) {
    asm volatile("mbarrier.init.shared.b64 [%0], %1;" :: "r"(a), "r"(cnt) : "memory");
}
__device__ __forceinline__ void mbar_arrive(u32 a) {
    asm volatile("mbarrier.arrive.shared.b64 _, [%0];" :: "r"(a) : "memory");
}
__device__ __forceinline__ void mbar_wait(u32 a, u32 parity) {
    asm volatile(
        "{ .reg .pred P;\n\t"
        "WL_%=:\n\t"
        "mbarrier.try_wait.parity.acquire.cta.shared::cta.b64 P, [%0], %1, 0x989680;\n\t"
        "@P bra.uni WD_%=;\n\t"
        "bra.uni WL_%=;\n\t"
        "WD_%=: }"
        :: "r"(a), "r"(parity) : "memory");
}

__global__ void __launch_bounds__(NTHR, 1)
rnn_f16_2g_kernel(const float* __restrict__ X,
                  const float* __restrict__ Wc,
                  const float* __restrict__ bc,
                  const float* __restrict__ Wo,
                  const float* __restrict__ bo,
                  float* __restrict__ out)
{
    extern __shared__ char smem[];
    const u32 sb = smem_u32(smem);
    const int tid  = threadIdx.x;
    const int lane = tid & 31;
    const int w    = tid >> 5;
    const long ctaB0 = (long)blockIdx.x * M_BLK;

    // warp -> n-tile range (start s_tab[w], count 2 or 3)
    const int s_tab[8] = {0, 3, 5, 8, 10, 12, 15, 17};
    const int s   = s_tab[w];
    const bool nt3 = (w == 0) | (w == 2) | (w == 5) | (w == 7);

    // ================= one-time init =================
    for (int i = tid; i < NPAD * ASTR; i += NTHR) {
        int n = i / ASTR, k = i - n * ASTR;
        float v = (n < H_HID && k < 278) ? Wc[k * H_HID + n] : 0.0f;
        *(__half*)(smem + SM_W + (u32)n * ASTRB + (u32)k * 2) = __float2half_rn(v);
    }
    for (int n = tid; n < NPAD; n += NTHR)
        *(float*)(smem + SM_BIAS + n * 4) = (n < H_HID) ? bc[n] : 0.0f;
    // zero all four A buffers (h regions must start 0)
    for (int i = tid * 16; i < 4 * ABUFSZ; i += NTHR * 16)
        *(float4*)(smem + i) = make_float4(0.f, 0.f, 0.f, 0.f);
    if (tid == 0) {
        mbar_init(sb + SM_MB, NTHR);
        mbar_init(sb + SM_MB + 8, NTHR);
    }
    __syncthreads();

    // x loader: thread owns (global row xm 0..31, 16 k-values)
    const int xm = tid >> 3;
    const int xk = (tid & 7) * 16;
    const int gx = xm >> 4;             // group of this thread's x row
    const float* Xrow = X + (ctaB0 + xm) * (long)T_SEQ * D_IN + xk;
    const u32 xga  = gx ? AG1 : AG0;
    const u32 xdst = (u32)(xm & 15) * ASTRB + (u32)xk * 2;

    {   // store x(0) -> group buf0
        u32 hh[8];
#pragma unroll
        for (int q = 0; q < 4; q++) {
            float4 f = *(const float4*)(Xrow + 4 * q);
            hh[2*q]   = cvt2h(f.x, f.y);
            hh[2*q+1] = cvt2h(f.z, f.w);
        }
        *(uint4*)(smem + xga + xdst)      = *(uint4*)&hh[0];
        *(uint4*)(smem + xga + xdst + 16) = *(uint4*)&hh[4];
    }

    // ============ per-lane ldmatrix offsets ============
    const int mat = lane >> 3, r8 = lane & 7;
    // A (m16): mats {m0-7@k0, m8-15@k0, m0-7@k8, m8-15@k8}
    const u32 aRel = (u32)(((mat & 1) << 3) + r8) * ASTRB + (u32)((mat >> 1) << 3) * 2;
    const u32 bB4 = sb + SM_W + (u32)(8 * s + ((mat >> 1) << 3) + r8) * ASTRB
                    + (u32)((mat & 1) << 3) * 2;
    const u32 bB2 = sb + SM_W + (u32)(8 * (s + 2) + r8) * ASTRB
                    + (u32)((mat & 1) << 3) * 2;

    // ---- pre-load all weight fragments into registers ----
    u32 wb[KTILES][4];
    u32 w3[KTILES][2];
#pragma unroll
    for (int kt = 0; kt < KTILES; kt++) {
        ldsm_x4(wb[kt], bB4 + (u32)kt * 32);
        if (nt3) ldsm_x2(w3[kt], bB2 + (u32)kt * 32);
    }
    __syncthreads();   // x(0) stores + W reads complete

    // epilogue mapping + hoisted bias
    const int eg = lane >> 2, et2 = (lane & 3) * 2;
    float2 bias_r[3];
#pragma unroll
    for (int j = 0; j < 3; j++)
        bias_r[j] = *(const float2*)(smem + SM_BIAS + (8 * (s + j) + et2) * 4);

    float c0[3][4], c1[3][4];
#pragma unroll
    for (int j = 0; j < 3; j++)
#pragma unroll
        for (int q = 0; q < 4; q++) { c0[j][q] = 0.0f; c1[j][q] = 0.0f; }

    u32 fa[2][4];   // A fragment double buffer (one m16 tile)

#define PHASE(GID, ABASE, C)                                                    \
    do {                                                                        \
        if (t > 0) mbar_wait(sb + SM_MB + (GID) * 8, (u32)((t - 1) & 1));       \
        const u32 rbase = sb + (ABASE) + rbo + aRel;                            \
        ldsm_x4(fa[0], rbase);                                                  \
        _Pragma("unroll")                                                       \
        for (int kt = 0; kt < KTILES; kt++) {                                   \
            const int cur = kt & 1;                                             \
            if (kt + 1 < KTILES) ldsm_x4(fa[cur ^ 1], rbase + (u32)(kt + 1) * 32); \
            mma_f16(C[0], fa[cur], wb[kt][0], wb[kt][1]);                       \
            mma_f16(C[1], fa[cur], wb[kt][2], wb[kt][3]);                       \
            if (nt3) mma_f16(C[2], fa[cur], w3[kt][0], w3[kt][1]);              \
        }                                                                       \
        _Pragma("unroll")                                                       \
        for (int j = 0; j < 3; j++) {                                           \
            if (j == 2 && !nt3) break;                                          \
            const int n = 8 * (s + j) + et2;                                    \
            float h00 = htanh(C[j][0] + bias_r[j].x);                           \
            float h01 = htanh(C[j][1] + bias_r[j].y);                           \
            float h10 = htanh(C[j][2] + bias_r[j].x);                           \
            float h11 = htanh(C[j][3] + bias_r[j].y);                           \
            u32 o0 = (ABASE) + wbo + (u32)eg * ASTRB + (u32)(D_IN + n) * 2;     \
            u32 o1 = o0 + 8 * ASTRB;                                            \
            *(u32*)(smem + o0) = cvt2h(h00, h01);                               \
            *(u32*)(smem + o1) = cvt2h(h10, h11);                               \
            if (last) {                                                         \
                *(float2*)(smem + SM_HF + (((u32)(GID) * 16 + eg) * NPAD + n) * 4) \
                    = make_float2(h00, h01);                                    \
                *(float2*)(smem + SM_HF + (((u32)(GID) * 16 + eg + 8) * NPAD + n) * 4) \
                    = make_float2(h10, h11);                                    \
            }                                                                   \
            C[j][0] = 0.f; C[j][1] = 0.f; C[j][2] = 0.f; C[j][3] = 0.f;         \
        }                                                                       \
        if (havex && gx == (GID)) {                                             \
            u32 hh[8];                                                          \
            _Pragma("unroll")                                                   \
            for (int q = 0; q < 4; q++) {                                       \
                hh[2*q]   = cvt2h(v[q].x, v[q].y);                              \
                hh[2*q+1] = cvt2h(v[q].z, v[q].w);                              \
            }                                                                   \
            *(uint4*)(smem + (ABASE) + wbo + xdst)      = *(uint4*)&hh[0];      \
            *(uint4*)(smem + (ABASE) + wbo + xdst + 16) = *(uint4*)&hh[4];      \
        }                                                                       \
        mbar_arrive(sb + SM_MB + (GID) * 8);                                    \
    } while (0)

    // ================= time loop (pipelined groups) =================
    for (int t = 0; t < T_SEQ; t++) {
        const u32 rbo = (u32)(t & 1) * ABUFSZ;   // read buffer offset
        const u32 wbo = ABUFSZ - rbo;            // write buffer offset
        const bool last = (t == T_SEQ - 1);

        // prefetch x(t+1)
        float4 v[4];
        const bool havex = (t + 1 < T_SEQ);
        if (havex) {
            const float* xp = Xrow + (long)(t + 1) * D_IN;
#pragma unroll
            for (int q = 0; q < 4; q++) v[q] = *(const float4*)(xp + 4 * q);
        }

        PHASE(0, AG0, c0);
        PHASE(1, AG1, c1);
    }
    __syncthreads();   // HF stash visible

    // ================= classifier head (fp32 h stash) =================
    for (int i = tid; i < M_BLK * O_OUT; i += NTHR) {
        const int b = i / O_OUT;
        const int o = i - b * O_OUT;
        float sacc = bo[o];
        const float* hrow = (const float*)(smem + SM_HF + (u32)b * NPAD * 4);
#pragma unroll 5
        for (int j = 0; j < H_HID; j++)
            sacc += hrow[j] * Wo[j * O_OUT + o];
        out[(ctaB0 + b) * O_OUT + o] = sacc;
    }
}

extern "C" void kernel_launch(void* const* d_in, const int* in_sizes, int n_in,
                              void* d_out, int out_size)
{
    const float* X  = (const float*)d_in[0];
    const float* Wc = (const float*)d_in[1];
    const float* bc = (const float*)d_in[2];
    const float* Wo = (const float*)d_in[3];
    const float* bo = (const float*)d_in[4];
    float* out = (float*)d_out;

    const int B = in_sizes[0] / (T_SEQ * D_IN);   // 4096

    cudaFuncSetAttribute(rnn_f16_2g_kernel,
                         cudaFuncAttributeMaxDynamicSharedMemorySize, SMEM_BYTES);

    rnn_f16_2g_kernel<<<B / M_BLK, NTHR, SMEM_BYTES>>>(X, Wc, bc, Wo, bo, out);
}

// round 14
// speedup vs baseline: 1.0196x; 1.0196x over previous
#include <cuda_runtime.h>
#include <cuda_fp16.h>
#include <cstdint>

// RNN h_t = tanh([x_t,h_{t-1}]@Wc + bc); out = h_T@Wo + bo
// B=4096, T=128, D=128, H=150, O=10.
// R14: single-pass fp16 mma.sync, weights in registers, K split by DEPENDENCY:
// x-part (kt 0-7, needs only x(t)) runs before the h-barrier wait and hides it;
// h-part (kt 8-17) is the only serialized piece. Separate mbarriers B_x / B_h.

#define T_SEQ 128
#define D_IN  128
#define H_HID 150
#define O_OUT 10
#define M_BLK 32
#define NPAD  160            // 20 n8-tiles
#define KT_X  8
#define KT_H  10
#define KTILES 18
#define ASTR  296
#define ASTRB 592
#define NTHR  256

// SMEM byte offsets
#define ABUF    18944                  // 32*592
#define SM_XB   0                      // x double buffer (2x)
#define SM_HB   37888                  // h double buffer (2x)
#define SM_W    75776                  // +2*ABUF
#define SM_BIAS 170496                 // +160*592
#define SM_HF   171136                 // +640 ; fp32 h stash [32][160]
#define SM_MB   191616                 // +32*640 ; B_h @ +0, B_x @ +8
#define SMEM_BYTES 191632

typedef unsigned int u32;

__device__ __forceinline__ u32 smem_u32(const void* p) {
    u32 a;
    asm("{ .reg .u64 t; cvta.to.shared.u64 t, %1; cvt.u32.u64 %0, t; }" : "=r"(a) : "l"(p));
    return a;
}
__device__ __forceinline__ void ldsm_x4(u32* r, u32 addr) {
    asm volatile("ldmatrix.sync.aligned.m8n8.x4.shared.b16 {%0,%1,%2,%3}, [%4];"
        : "=r"(r[0]), "=r"(r[1]), "=r"(r[2]), "=r"(r[3]) : "r"(addr));
}
__device__ __forceinline__ void ldsm_x2(u32* r, u32 addr) {
    asm volatile("ldmatrix.sync.aligned.m8n8.x2.shared.b16 {%0,%1}, [%2];"
        : "=r"(r[0]), "=r"(r[1]) : "r"(addr));
}
__device__ __forceinline__ void mma_f16(float* c, const u32* a, u32 b0, u32 b1) {
    asm volatile("mma.sync.aligned.m16n8k16.row.col.f32.f16.f16.f32 "
        "{%0,%1,%2,%3}, {%4,%5,%6,%7}, {%8,%9}, {%0,%1,%2,%3};"
        : "+f"(c[0]), "+f"(c[1]), "+f"(c[2]), "+f"(c[3])
        : "r"(a[0]), "r"(a[1]), "r"(a[2]), "r"(a[3]), "r"(b0), "r"(b1));
}
__device__ __forceinline__ u32 cvt2h(float a, float b) {   // pack fp16x2 (lo=a, hi=b)
    u32 r;
    asm("cvt.rn.f16x2.f32 %0, %1, %2;" : "=r"(r) : "f"(b), "f"(a));
    return r;
}
__device__ __forceinline__ float htanh(float x) {          // MUFU.TANH
    float r;
    asm("tanh.approx.f32 %0, %1;" : "=f"(r) : "f"(x));
    return r;
}
__device__ __forceinline__ void mbar_init(u32 a, u32 cnt) {
    asm volatile("mbarrier.init.shared.b64 [%0], %1;" :: "r"(a), "r"(cnt) : "memory");
}
__device__ __forceinline__ void mbar_arrive(u32 a) {
    asm volatile("mbarrier.arrive.shared.b64 _, [%0];" :: "r"(a) : "memory");
}
__device__ __forceinline__ void mbar_wait(u32 a, u32 parity) {
    asm volatile(
        "{ .reg .pred P;\n\t"
        "WL_%=:\n\t"
        "mbarrier.try_wait.parity.acquire.cta.shared::cta.b64 P, [%0], %1, 0x989680;\n\t"
        "@P bra.uni WD_%=;\n\t"
        "bra.uni WL_%=;\n\t"
        "WD_%=: }"
        :: "r"(a), "r"(parity) : "memory");
}

__global__ void __launch_bounds__(NTHR, 1)
rnn_f16_ksplit_kernel(const float* __restrict__ X,
                      const float* __restrict__ Wc,
                      const float* __restrict__ bc,
                      const float* __restrict__ Wo,
                      const float* __restrict__ bo,
                      float* __restrict__ out)
{
    extern __shared__ char smem[];
    const u32 sb = smem_u32(smem);
    const int tid  = threadIdx.x;
    const int lane = tid & 31;
    const int w    = tid >> 5;
    const long ctaB0 = (long)blockIdx.x * M_BLK;

    // warp -> n-tile range (start s_tab[w], count 2 or 3)
    const int s_tab[8] = {0, 3, 5, 8, 10, 12, 15, 17};
    const int s   = s_tab[w];
    const bool nt3 = (w == 0) | (w == 2) | (w == 5) | (w == 7);

    // ================= one-time init =================
    for (int i = tid; i < NPAD * ASTR; i += NTHR) {
        int n = i / ASTR, k = i - n * ASTR;
        float v = (n < H_HID && k < 278) ? Wc[k * H_HID + n] : 0.0f;
        *(__half*)(smem + SM_W + (u32)n * ASTRB + (u32)k * 2) = __float2half_rn(v);
    }
    for (int n = tid; n < NPAD; n += NTHR)
        *(float*)(smem + SM_BIAS + n * 4) = (n < H_HID) ? bc[n] : 0.0f;
    // zero both h buffers (h(-1) = 0) and x buffers
    for (int i = tid * 16; i < 4 * ABUF; i += NTHR * 16)
        *(float4*)(smem + i) = make_float4(0.f, 0.f, 0.f, 0.f);
    if (tid == 0) {
        mbar_init(sb + SM_MB, NTHR);       // B_h
        mbar_init(sb + SM_MB + 8, NTHR);   // B_x
    }
    __syncthreads();

    // x loader: thread owns (row xm, 16 k-values)
    const int xm = tid >> 3;
    const int xk = (tid & 7) * 16;
    const float* Xrow = X + (ctaB0 + xm) * (long)T_SEQ * D_IN + xk;
    const u32 xdst = (u32)xm * ASTRB + (u32)xk * 2;   // relative to x buffer base

    {   // store x(0) -> xbuf[0]
        u32 hh[8];
#pragma unroll
        for (int q = 0; q < 4; q++) {
            float4 f = *(const float4*)(Xrow + 4 * q);
            hh[2*q]   = cvt2h(f.x, f.y);
            hh[2*q+1] = cvt2h(f.z, f.w);
        }
        *(uint4*)(smem + SM_XB + xdst)      = *(uint4*)&hh[0];
        *(uint4*)(smem + SM_XB + xdst + 16) = *(uint4*)&hh[4];
    }

    // ============ per-lane ldmatrix offsets ============
    const int mat = lane >> 3, r8 = lane & 7;
    const u32 aRel = (u32)(16 * 0 + ((mat & 1) << 3) + r8) * ASTRB
                     + (u32)((mat >> 1) << 3) * 2;      // m-tile 0
    const u32 aRel1 = aRel + 16 * ASTRB;                // m-tile 1
    const u32 bB4 = sb + SM_W + (u32)(8 * s + ((mat >> 1) << 3) + r8) * ASTRB
                    + (u32)((mat & 1) << 3) * 2;
    const u32 bB2 = sb + SM_W + (u32)(8 * (s + 2) + r8) * ASTRB
                    + (u32)((mat & 1) << 3) * 2;

    // ---- pre-load all weight fragments into registers ----
    u32 wb[KTILES][4];
    u32 w3[KTILES][2];
#pragma unroll
    for (int kt = 0; kt < KTILES; kt++) {
        ldsm_x4(wb[kt], bB4 + (u32)kt * 32);
        if (nt3) ldsm_x2(w3[kt], bB2 + (u32)kt * 32);
    }
    __syncthreads();   // x(0) stores + W reads complete

    // epilogue mapping + hoisted bias
    const int eg = lane >> 2, et2 = (lane & 3) * 2;
    float2 bias_r[3];
#pragma unroll
    for (int j = 0; j < 3; j++)
        bias_r[j] = *(const float2*)(smem + SM_BIAS + (8 * (s + j) + et2) * 4);

    float c[2][3][4];
#pragma unroll
    for (int mt = 0; mt < 2; mt++)
#pragma unroll
        for (int j = 0; j < 3; j++)
#pragma unroll
            for (int q = 0; q < 4; q++) c[mt][j][q] = 0.0f;

    u32 fa[2][2][4];   // A fragment double buffer

#define LOADA(B, BASE, KO)                           \
    do {                                             \
        ldsm_x4(fa[B][0], (BASE) + (KO));            \
        ldsm_x4(fa[B][1], (BASE) + 16 * ASTRB + (KO)); \
    } while (0)

#define MMAF(B, KT)                                                 \
    do {                                                            \
        mma_f16(c[0][0], fa[B][0], wb[KT][0], wb[KT][1]);           \
        mma_f16(c[1][0], fa[B][1], wb[KT][0], wb[KT][1]);           \
        mma_f16(c[0][1], fa[B][0], wb[KT][2], wb[KT][3]);           \
        mma_f16(c[1][1], fa[B][1], wb[KT][2], wb[KT][3]);           \
        if (nt3) {                                                  \
            mma_f16(c[0][2], fa[B][0], w3[KT][0], w3[KT][1]);       \
            mma_f16(c[1][2], fa[B][1], w3[KT][0], w3[KT][1]);       \
        }                                                           \
    } while (0)

    // ================= time loop =================
    for (int t = 0; t < T_SEQ; t++) {
        const u32 xrb = sb + SM_XB + (u32)(t & 1) * ABUF + aRel;        // read x(t)
        const u32 hrb = sb + SM_HB + (u32)((t + 1) & 1) * ABUF + aRel;  // read h(t-1)
        const u32 hwb = SM_HB + (u32)(t & 1) * ABUF;                    // write h(t)
        const u32 xwb = SM_XB + (u32)((t + 1) & 1) * ABUF;              // write x(t+1)
        const u32 pv  = (u32)((t - 1) & 1);
        const bool last = (t == T_SEQ - 1);

        // issue x(t+1) global loads first (long latency, no deps)
        float4 v[4];
        const bool havex = (t + 1 < T_SEQ);
        if (havex) {
            const float* xp = Xrow + (long)(t + 1) * D_IN;
#pragma unroll
            for (int q = 0; q < 4; q++) v[q] = *(const float4*)(xp + 4 * q);
        }

        // ---- x-part: kt 0..7 — depends only on x(t) ----
        if (t > 0) mbar_wait(sb + SM_MB + 8, pv);      // B_x
        LOADA(0, xrb, 0u);
#pragma unroll
        for (int kt = 0; kt < KT_X; kt++) {
            const int cur = kt & 1;
            if (kt + 1 < KT_X) LOADA(cur ^ 1, xrb, (u32)(kt + 1) * 32);
            MMAF(cur, kt);
        }

        // ---- h-part: kt 8..17 — the only piece that needs h(t-1) ----
        if (t > 0) mbar_wait(sb + SM_MB, pv);          // B_h
        LOADA(0, hrb, 0u);
#pragma unroll
        for (int kt = 0; kt < KT_H; kt++) {
            const int cur = kt & 1;
            if (kt + 1 < KT_H) LOADA(cur ^ 1, hrb, (u32)(kt + 1) * 32);
            MMAF(cur, KT_X + kt);
        }

        // ---- epilogue: h(t) = tanh(acc + bias) -> hbuf[t&1] ----
#pragma unroll
        for (int mt = 0; mt < 2; mt++) {
            const int em = 16 * mt + eg;
#pragma unroll
            for (int j = 0; j < 3; j++) {
                if (j == 2 && !nt3) break;
                const int n = 8 * (s + j) + et2;
                float h00 = htanh(c[mt][j][0] + bias_r[j].x);
                float h01 = htanh(c[mt][j][1] + bias_r[j].y);
                float h10 = htanh(c[mt][j][2] + bias_r[j].x);
                float h11 = htanh(c[mt][j][3] + bias_r[j].y);
                u32 o0 = hwb + (u32)em * ASTRB + (u32)n * 2;
                u32 o1 = o0 + 8 * ASTRB;
                *(u32*)(smem + o0) = cvt2h(h00, h01);
                *(u32*)(smem + o1) = cvt2h(h10, h11);
                if (last) {
                    *(float2*)(smem + SM_HF + ((u32)em * NPAD + n) * 4)
                        = make_float2(h00, h01);
                    *(float2*)(smem + SM_HF + ((u32)(em + 8) * NPAD + n) * 4)
                        = make_float2(h10, h11);
                }
                c[mt][j][0] = 0.f; c[mt][j][1] = 0.f;
                c[mt][j][2] = 0.f; c[mt][j][3] = 0.f;
            }
        }
        mbar_arrive(sb + SM_MB);                       // B_h: h(t) published

        // ---- store x(t+1) -> xbuf[(t+1)&1] ----
        if (havex) {
            u32 hh[8];
#pragma unroll
            for (int q = 0; q < 4; q++) {
                hh[2*q]   = cvt2h(v[q].x, v[q].y);
                hh[2*q+1] = cvt2h(v[q].z, v[q].w);
            }
            *(uint4*)(smem + xwb + xdst)      = *(uint4*)&hh[0];
            *(uint4*)(smem + xwb + xdst + 16) = *(uint4*)&hh[4];
        }
        mbar_arrive(sb + SM_MB + 8);                   // B_x: x(t+1) published
    }
    __syncthreads();   // HF stash visible

    // ================= classifier head (fp32 h stash) =================
    for (int i = tid; i < M_BLK * O_OUT; i += NTHR) {
        const int b = i / O_OUT;
        const int o = i - b * O_OUT;
        float sacc = bo[o];
        const float* hrow = (const float*)(smem + SM_HF + (u32)b * NPAD * 4);
#pragma unroll 5
        for (int j = 0; j < H_HID; j++)
            sacc += hrow[j] * Wo[j * O_OUT + o];
        out[(ctaB0 + b) * O_OUT + o] = sacc;
    }
}

extern "C" void kernel_launch(void* const* d_in, const int* in_sizes, int n_in,
                              void* d_out, int out_size)
{
    const float* X  = (const float*)d_in[0];
    const float* Wc = (const float*)d_in[1];
    const float* bc = (const float*)d_in[2];
    const float* Wo = (const float*)d_in[3];
    const float* bo = (const float*)d_in[4];
    float* out = (float*)d_out;

    const int B = in_sizes[0] / (T_SEQ * D_IN);   // 4096

    cudaFuncSetAttribute(rnn_f16_ksplit_kernel,
                         cudaFuncAttributeMaxDynamicSharedMemorySize, SMEM_BYTES);

    rnn_f16_ksplit_kernel<<<B / M_BLK, NTHR, SMEM_BYTES>>>(X, Wc, bc, Wo, bo, out);
}